// round 8
// baseline (speedup 1.0000x reference)
#include <cuda_runtime.h>
#include <cuda_bf16.h>

// MSDeformAttn on GB300 (sm_103a) — 2-line-per-LDG gather layout
//   B=2, Hd=8, C=32, P=4, levels=4
//   SHAPES = [(100,150),(50,75),(25,38),(13,19)], L = Q = 19947
//
// Binder identified in rounds 1-6: L1tex wavefront replays. The old layout
// (4 groups x 8 lanes x float4) made every gather LDG.128 touch 4 distinct
// 128B lines -> 1 + 3x2.07 replay cyc/instr -> ~138us floor (matches plateau).
// This version uses 2 groups x 16 lanes x float2: each corner gather is an
// LDG.64 touching 2 lines (1 + 1x2.07 cyc), cutting the L1 wavefront-replay
// cost ~40% at the price of ~20% more issue work (each group walks 2 points
// per level sequentially).
//
// Corner loads UNCONDITIONAL (clamped indices); out-of-bounds corners zeroed
// through bilinear weights (reference clip+mask semantics).

#define QTOT 19947
#define LTOT 19947
#define HD   8
#define CH   32
#define ROWF2 (HD * CH / 2)   // float2 stride between spatial positions = 128

__global__ void __launch_bounds__(256, 8)
msda_kernel(const float* __restrict__ value,
            const float* __restrict__ loc,
            const float* __restrict__ attw,
            float* __restrict__ out)
{
    const int warp = threadIdx.x >> 5;
    const int lane = threadIdx.x & 31;
    const int q = blockIdx.x * 8 + warp;
    if (q >= QTOT) return;                 // uniform across warp

    const int bh = blockIdx.y;             // b*8 + h
    const int b  = bh >> 3;
    const int h  = bh & 7;

    const int group = lane >> 4;           // 0 or 1: point-pair selector
    const int sub   = lane & 15;           // channel pair (2*sub, 2*sub+1)

    const int qbh = (b * QTOT + q) * HD + h;

    // per-lane pointers into this query's loc/weight arrays (16 entries: l*4+p)
    const float2* locp = (const float2*)loc + (size_t)qbh * 16;
    const float*  awp  = attw + (size_t)qbh * 16;

    const int Hs[4] = {100, 50, 25, 13};
    const int Ws[4] = {150, 75, 38, 19};
    const int Ss[4] = {0, 15000, 18750, 19700};

    // per-lane gather base: (b, h, channel-pair)
    const float2* vbase = (const float2*)(value + ((size_t)b * LTOT) * (HD * CH)
                                                + (size_t)h * CH) + sub;

    float accx = 0.f, accy = 0.f;

#pragma unroll
    for (int l = 0; l < 4; ++l) {
        const int Hh = Hs[l];
        const int Ww = Ws[l];
        const float2* lb = vbase + Ss[l] * ROWF2;

#pragma unroll
        for (int jj = 0; jj < 2; ++jj) {
            const int p  = group * 2 + jj;           // point index 0..3
            const int lp = l * 4 + p;

            const float2 xy = locp[lp];              // broadcast within 16-lane group
            const float  wt = awp[lp];

            const float x = xy.x * (float)Ww - 0.5f;
            const float y = xy.y * (float)Hh - 0.5f;
            const float xf = floorf(x);
            const float yf = floorf(y);
            const float dx = x - xf;
            const float dy = y - yf;
            const int x0 = (int)xf;                  // in [-1, Ww-1]
            const int y0 = (int)yf;                  // in [-1, Hh-1]

            // validity folded into weights
            const float fx0 = ((unsigned)x0       < (unsigned)Ww) ? 1.f : 0.f;
            const float fx1 = ((unsigned)(x0 + 1) < (unsigned)Ww) ? 1.f : 0.f;
            const float fy0 = ((unsigned)y0       < (unsigned)Hh) ? 1.f : 0.f;
            const float fy1 = ((unsigned)(y0 + 1) < (unsigned)Hh) ? 1.f : 0.f;

            const float gy0 = wt * (1.f - dy) * fy0;
            const float gy1 = wt * dy * fy1;
            const float gx0 = (1.f - dx) * fx0;
            const float gx1 = dx * fx1;
            const float w00 = gy0 * gx0;
            const float w01 = gy0 * gx1;
            const float w10 = gy1 * gx0;
            const float w11 = gy1 * gx1;

            // clamped indices
            const int x0c = max(x0, 0);
            const int x1c = min(x0 + 1, Ww - 1);
            const int y0c = max(y0, 0);
            const int y1c = min(y0 + 1, Hh - 1);

            const int r00 = (y0c * Ww + x0c) * ROWF2;
            const int xs  = (x1c - x0c) * ROWF2;        // 0 or 128
            const int ys  = (y1c - y0c) * (Ww * ROWF2); // 0 or Ww*128

            // interleaved loads / FMAs (<=2 float2 temporaries live)
            const float2 va = lb[r00];
            const float2 vb = lb[r00 + xs];
            accx += w00 * va.x; accy += w00 * va.y;
            const float2 vc = lb[r00 + ys];
            accx += w01 * vb.x; accy += w01 * vb.y;
            const float2 vd = lb[r00 + ys + xs];
            accx += w10 * vc.x; accy += w10 * vc.y;
            accx += w11 * vd.x; accy += w11 * vd.y;
        }
    }

    // ---- reduce the 2 point-groups (lanes s and s+16) ----
    accx += __shfl_xor_sync(0xffffffffu, accx, 16);
    accy += __shfl_xor_sync(0xffffffffu, accy, 16);

    if (group == 0) {
        // out[b, q, h*32 + 2*sub .. +2) : 16 lanes x 8B = one 128B store
        float2 r; r.x = accx; r.y = accy;
        *(float2*)(out + (size_t)qbh * CH + sub * 2) = r;
    }
}

extern "C" void kernel_launch(void* const* d_in, const int* in_sizes, int n_in,
                              void* d_out, int out_size)
{
    const float* value = (const float*)d_in[0];
    const float* loc   = (const float*)d_in[3];
    const float* attw  = (const float*)d_in[4];
    float* out = (float*)d_out;

    dim3 grid((QTOT + 7) / 8, 2 * HD, 1);
    msda_kernel<<<grid, 256>>>(value, loc, attw, out);
}

// round 9
// speedup vs baseline: 1.2024x; 1.2024x over previous
#include <cuda_runtime.h>
#include <cuda_bf16.h>

// MSDeformAttn on GB300 (sm_103a) — dedup point-setup via SMEM
//   B=2, Hd=8, C=32, P=4, levels=4
//   SHAPES = [(100,150),(50,75),(25,38),(13,19)], L = Q = 19947
//
// Proven-best gather layout (R1/R4): one warp per (b,q,h), 4 groups x 8
// lanes x float4 -> each corner load is a fully-used 128B line per group.
// New: the per-point scalar work (bilinear weights + clamped corner offsets),
// previously duplicated across all 8 lanes of a group (~120 redundant
// inst/thread), is computed ONCE by lanes 0-15 (one lane per (level,point))
// and staged in shared memory; the gather loop fetches it with two broadcast
// LDS.128 per level. Out-of-bounds corners are zeroed through the weights
// (reference clip+mask semantics); indices are pre-clamped.

#define QTOT 19947
#define LTOT 19947
#define HD   8
#define CH   32
#define ROWF4 (HD * CH / 4)   // float4s between spatial positions = 64

__global__ void __launch_bounds__(256, 8)
msda_kernel(const float* __restrict__ value,
            const float* __restrict__ loc,
            const float* __restrict__ attw,
            float* __restrict__ out)
{
    __shared__ float4 sw[8][16];   // folded bilinear weights per (warp, l*4+p)
    __shared__ int4   sr[8][16];   // clamped corner offsets (float4 units, incl. level start)

    const int warp = threadIdx.x >> 5;
    const int lane = threadIdx.x & 31;
    const int q = blockIdx.x * 8 + warp;
    if (q >= QTOT) return;                 // uniform across warp

    const int bh = blockIdx.y;             // b*8 + h
    const int b  = bh >> 3;
    const int h  = bh & 7;
    const int qbh = (b * QTOT + q) * HD + h;

    // ---- phase 1: lanes 0-15, one (level,point) each ----
    if (lane < 16) {
        const int l = lane >> 2;
        // compile-time tables via selects (avoid dynamic local-array indexing)
        const int Hh = (l == 0) ? 100 : (l == 1) ? 50 : (l == 2) ? 25 : 13;
        const int Ww = (l == 0) ? 150 : (l == 1) ? 75 : (l == 2) ? 38 : 19;
        const int S  = (l == 0) ? 0   : (l == 1) ? 15000 : (l == 2) ? 18750 : 19700;

        const float2 xy = ((const float2*)loc)[(size_t)qbh * 16 + lane]; // 16 lanes -> 128B
        const float  wt = attw[(size_t)qbh * 16 + lane];                 // 16 lanes -> 64B

        const float x = xy.x * (float)Ww - 0.5f;
        const float y = xy.y * (float)Hh - 0.5f;
        const float xf = floorf(x);
        const float yf = floorf(y);
        const float dx = x - xf;
        const float dy = y - yf;
        const int x0 = (int)xf;            // in [-1, Ww-1]
        const int y0 = (int)yf;            // in [-1, Hh-1]

        const float fx0 = ((unsigned)x0       < (unsigned)Ww) ? 1.f : 0.f;
        const float fx1 = ((unsigned)(x0 + 1) < (unsigned)Ww) ? 1.f : 0.f;
        const float fy0 = ((unsigned)y0       < (unsigned)Hh) ? 1.f : 0.f;
        const float fy1 = ((unsigned)(y0 + 1) < (unsigned)Hh) ? 1.f : 0.f;

        const float gy0 = wt * (1.f - dy) * fy0;
        const float gy1 = wt * dy * fy1;
        const float gx0 = (1.f - dx) * fx0;
        const float gx1 = dx * fx1;

        sw[warp][lane] = make_float4(gy0 * gx0, gy0 * gx1, gy1 * gx0, gy1 * gx1);

        const int x0c = max(x0, 0);
        const int x1c = min(x0 + 1, Ww - 1);
        const int y0c = max(y0, 0);
        const int y1c = min(y0 + 1, Hh - 1);
        const int row0 = S + y0c * Ww;
        const int row1 = S + y1c * Ww;
        sr[warp][lane] = make_int4((row0 + x0c) * ROWF4, (row0 + x1c) * ROWF4,
                                   (row1 + x0c) * ROWF4, (row1 + x1c) * ROWF4);
    }
    __syncwarp();

    // ---- phase 2: gather loop (4 groups x 8 lanes x float4) ----
    const int group = lane >> 3;           // point index within each level
    const int sub   = lane & 7;            // channel quad

    const float4* vbase = (const float4*)(value + ((size_t)b * LTOT) * (HD * CH)
                                                + (size_t)h * CH) + sub;

    float4 acc = make_float4(0.f, 0.f, 0.f, 0.f);

#pragma unroll
    for (int l = 0; l < 4; ++l) {
        const float4 w = sw[warp][l * 4 + group];   // broadcast LDS.128
        const int4   r = sr[warp][l * 4 + group];   // broadcast LDS.128

        // interleaved loads/FMAs (<=2 float4 temporaries live)
        const float4 va = vbase[r.x];
        const float4 vb = vbase[r.y];
        acc.x += w.x * va.x; acc.y += w.x * va.y; acc.z += w.x * va.z; acc.w += w.x * va.w;
        const float4 vc = vbase[r.z];
        acc.x += w.y * vb.x; acc.y += w.y * vb.y; acc.z += w.y * vb.z; acc.w += w.y * vb.w;
        const float4 vd = vbase[r.w];
        acc.x += w.z * vc.x; acc.y += w.z * vc.y; acc.z += w.z * vc.z; acc.w += w.z * vc.w;
        acc.x += w.w * vd.x; acc.y += w.w * vd.y; acc.z += w.w * vd.z; acc.w += w.w * vd.w;
    }

    // ---- reduce the 4 point-groups (lanes s, s+8, s+16, s+24) ----
    acc.x += __shfl_xor_sync(0xffffffffu, acc.x, 8);
    acc.y += __shfl_xor_sync(0xffffffffu, acc.y, 8);
    acc.z += __shfl_xor_sync(0xffffffffu, acc.z, 8);
    acc.w += __shfl_xor_sync(0xffffffffu, acc.w, 8);
    acc.x += __shfl_xor_sync(0xffffffffu, acc.x, 16);
    acc.y += __shfl_xor_sync(0xffffffffu, acc.y, 16);
    acc.z += __shfl_xor_sync(0xffffffffu, acc.z, 16);
    acc.w += __shfl_xor_sync(0xffffffffu, acc.w, 16);

    if (group == 0) {
        // out[b, q, h*32 + 4*sub .. +4) : 8 lanes x 16B = one 128B store
        *(float4*)(out + (size_t)qbh * CH + sub * 4) = acc;
    }
}

extern "C" void kernel_launch(void* const* d_in, const int* in_sizes, int n_in,
                              void* d_out, int out_size)
{
    const float* value = (const float*)d_in[0];
    const float* loc   = (const float*)d_in[3];
    const float* attw  = (const float*)d_in[4];
    float* out = (float*)d_out;

    dim3 grid((QTOT + 7) / 8, 2 * HD, 1);
    msda_kernel<<<grid, 256>>>(value, loc, attw, out);
}

// round 10
// speedup vs baseline: 1.3417x; 1.1159x over previous
#include <cuda_runtime.h>
#include <cuda_bf16.h>

// MSDeformAttn on GB300 (sm_103a) — LDG.64 gather + smem-staged setup
//   B=2, Hd=8, C=32, P=4, levels=4
//   SHAPES = [(100,150),(50,75),(25,38),(13,19)], L = Q = 19947
//
// Evidence through R8: binder is L1tex wavefront service; within-LDG replay
// wavefronts cost ~2.07 cyc vs 1.0 cross-LDG. The float4/8-lane layout (4
// lines per LDG.128) pays max replay; this version gathers float2 with
// 16-lane groups (2 lines per LDG.64, ~3.1 cyc/instr) -> L1 floor ~113us.
// Scalar work stays low via smem-staged per-point weights/offsets (computed
// once by lanes 0-15), and latency is covered by batching all 8 corner loads
// of a level (2 points) before any consume.

#define QTOT 19947
#define LTOT 19947
#define HD   8
#define CH   32
#define ROWF2 (HD * CH / 2)   // float2 stride between spatial positions = 128

__global__ void __launch_bounds__(256, 7)
msda_kernel(const float* __restrict__ value,
            const float* __restrict__ loc,
            const float* __restrict__ attw,
            float* __restrict__ out)
{
    __shared__ float4 sw[8][16];   // folded bilinear weights per (warp, l*4+p)
    __shared__ int4   sr[8][16];   // clamped corner offsets (float2 units, incl. level start)

    const int warp = threadIdx.x >> 5;
    const int lane = threadIdx.x & 31;
    const int q = blockIdx.x * 8 + warp;
    if (q >= QTOT) return;                 // uniform across warp

    const int bh = blockIdx.y;             // b*8 + h
    const int b  = bh >> 3;
    const int h  = bh & 7;
    const int qbh = (b * QTOT + q) * HD + h;

    // ---- phase 1: lanes 0-15 compute one (level,point) each ----
    if (lane < 16) {
        const int l = lane >> 2;
        const int Hh = (l == 0) ? 100 : (l == 1) ? 50 : (l == 2) ? 25 : 13;
        const int Ww = (l == 0) ? 150 : (l == 1) ? 75 : (l == 2) ? 38 : 19;
        const int S  = (l == 0) ? 0   : (l == 1) ? 15000 : (l == 2) ? 18750 : 19700;

        const float2 xy = ((const float2*)loc)[(size_t)qbh * 16 + lane]; // coalesced 128B
        const float  wt = attw[(size_t)qbh * 16 + lane];                 // coalesced 64B

        const float x = xy.x * (float)Ww - 0.5f;
        const float y = xy.y * (float)Hh - 0.5f;
        const float xf = floorf(x);
        const float yf = floorf(y);
        const float dx = x - xf;
        const float dy = y - yf;
        const int x0 = (int)xf;            // in [-1, Ww-1]
        const int y0 = (int)yf;            // in [-1, Hh-1]

        const float fx0 = ((unsigned)x0       < (unsigned)Ww) ? 1.f : 0.f;
        const float fx1 = ((unsigned)(x0 + 1) < (unsigned)Ww) ? 1.f : 0.f;
        const float fy0 = ((unsigned)y0       < (unsigned)Hh) ? 1.f : 0.f;
        const float fy1 = ((unsigned)(y0 + 1) < (unsigned)Hh) ? 1.f : 0.f;

        const float gy0 = wt * (1.f - dy) * fy0;
        const float gy1 = wt * dy * fy1;
        const float gx0 = (1.f - dx) * fx0;
        const float gx1 = dx * fx1;

        sw[warp][lane] = make_float4(gy0 * gx0, gy0 * gx1, gy1 * gx0, gy1 * gx1);

        const int x0c = max(x0, 0);
        const int x1c = min(x0 + 1, Ww - 1);
        const int y0c = max(y0, 0);
        const int y1c = min(y0 + 1, Hh - 1);
        const int row0 = S + y0c * Ww;
        const int row1 = S + y1c * Ww;
        sr[warp][lane] = make_int4((row0 + x0c) * ROWF2, (row0 + x1c) * ROWF2,
                                   (row1 + x0c) * ROWF2, (row1 + x1c) * ROWF2);
    }
    __syncwarp();

    // ---- phase 2: gather (2 groups x 16 lanes x float2; 2 lines per LDG.64) ----
    const int group = lane >> 4;           // point-pair selector: points {2g, 2g+1}
    const int sub   = lane & 15;           // channel pair (2*sub, 2*sub+1)

    const float2* vbase = (const float2*)(value + ((size_t)b * LTOT) * (HD * CH)
                                                + (size_t)h * CH) + sub;

    float accx = 0.f, accy = 0.f;

#pragma unroll
    for (int l = 0; l < 4; ++l) {
        const int ia = l * 4 + group * 2;      // point 2g
        const int ib = ia + 1;                 // point 2g+1

        // both points' offsets first, then ALL 8 loads back-to-back (MLP=8)
        const int4 ra = sr[warp][ia];
        const int4 rb = sr[warp][ib];

        const float2 va0 = vbase[ra.x];
        const float2 va1 = vbase[ra.y];
        const float2 va2 = vbase[ra.z];
        const float2 va3 = vbase[ra.w];
        const float2 vb0 = vbase[rb.x];
        const float2 vb1 = vbase[rb.y];
        const float2 vb2 = vbase[rb.z];
        const float2 vb3 = vbase[rb.w];

        const float4 wa = sw[warp][ia];
        const float4 wb = sw[warp][ib];

        accx += wa.x * va0.x; accy += wa.x * va0.y;
        accx += wa.y * va1.x; accy += wa.y * va1.y;
        accx += wa.z * va2.x; accy += wa.z * va2.y;
        accx += wa.w * va3.x; accy += wa.w * va3.y;
        accx += wb.x * vb0.x; accy += wb.x * vb0.y;
        accx += wb.y * vb1.x; accy += wb.y * vb1.y;
        accx += wb.z * vb2.x; accy += wb.z * vb2.y;
        accx += wb.w * vb3.x; accy += wb.w * vb3.y;
    }

    // ---- reduce the 2 point-groups (lanes s and s+16) ----
    accx += __shfl_xor_sync(0xffffffffu, accx, 16);
    accy += __shfl_xor_sync(0xffffffffu, accy, 16);

    if (group == 0) {
        // out[b, q, h*32 + 2*sub .. +2) : 16 lanes x 8B = one 128B store
        float2 r; r.x = accx; r.y = accy;
        *(float2*)(out + (size_t)qbh * CH + sub * 2) = r;
    }
}

extern "C" void kernel_launch(void* const* d_in, const int* in_sizes, int n_in,
                              void* d_out, int out_size)
{
    const float* value = (const float*)d_in[0];
    const float* loc   = (const float*)d_in[3];
    const float* attw  = (const float*)d_in[4];
    float* out = (float*)d_out;

    dim3 grid((QTOT + 7) / 8, 2 * HD, 1);
    msda_kernel<<<grid, 256>>>(value, loc, attw, out);
}